// round 1
// baseline (speedup 1.0000x reference)
#include <cuda_runtime.h>
#include <math.h>

// Problem constants (B=1)
#define LL   2048
#define DD   512
#define KK   64
#define TWOK 128
#define CH   128   // chunk length
#define NCH  16    // number of chunks

static __device__ float g_H  [LL*DD];        // hidden after first encoder GEMM (reused ke/qe)
static __device__ float g_pk [LL*KK];        // key phase
static __device__ float g_pq [LL*KK];        // query phase
static __device__ float g_amp[LL*KK];        // amplitude
static __device__ float g_V  [LL*DD];        // values
static __device__ float g_Qc [LL*TWOK];      // [qr | qi]
static __device__ float g_Kc [LL*TWOK];      // [kr | ki]
static __device__ float g_G  [NCH*TWOK*DD];  // per-chunk K^T V
static __device__ float g_Sx [NCH*TWOK*DD];  // exclusive prefix states
static __device__ float g_P  [NCH*CH*CH];    // masked intra-chunk scores
static __device__ float g_ret[LL*DD];        // retrieved (normalized)
static __device__ float g_rn [LL*DD];        // layernormed retrieved

#define PI_F 3.14159265358979323846f

// ---------------------------------------------------------------------------
// Generic tiled fp32 GEMM:  C = epi( [C +] opA(A) @ opB(B) + bias )
// A: M x Kd (or Kd x M if TRA), B: Kd x N (or N x Kd if TRB), row-major, ld given.
// Batched via blockIdx.z with element strides sA/sB/sC.
// EPI: 0 none, 1 exact GELU, 2 tanh*pi, 3 softplus+0.1, 4 +X residual,
//      5 causal mask (local in-batch row/col), 6 scale by rsqrt((l+1)*KK)
// ---------------------------------------------------------------------------
template<int BM, int BN, int BK, int TM, int TN, int EPI, bool TRA, bool TRB, bool ACC>
__launch_bounds__(256)
__global__ void gemm_k(const float* __restrict__ A, const float* __restrict__ B,
                       const float* __restrict__ bias, const float* __restrict__ X,
                       float* __restrict__ C,
                       int M, int N, int Kd, int lda, int ldb, int ldc,
                       long sA, long sB, long sC)
{
    __shared__ float As[BK][BM + 1];
    __shared__ float Bs[BK][BN];

    const int NT  = (BM / TM) * (BN / TN);   // = 256
    const int tid = threadIdx.x;
    const int tx  = tid % (BN / TN);
    const int ty  = tid / (BN / TN);
    const int z   = blockIdx.z;

    A += (long)z * sA;
    B += (long)z * sB;
    C += (long)z * sC;

    const int m0 = blockIdx.y * BM;
    const int n0 = blockIdx.x * BN;

    float acc[TM][TN];
#pragma unroll
    for (int i = 0; i < TM; i++)
#pragma unroll
        for (int j = 0; j < TN; j++) acc[i][j] = 0.f;

    for (int k0 = 0; k0 < Kd; k0 += BK) {
        if (TRA) {
#pragma unroll
            for (int i = tid; i < BK * BM; i += NT) {
                int k = i / BM, m = i % BM;
                As[k][m] = A[(long)(k0 + k) * lda + m0 + m];
            }
        } else {
#pragma unroll
            for (int i = tid; i < BK * BM; i += NT) {
                int m = i / BK, k = i % BK;
                As[k][m] = A[(long)(m0 + m) * lda + k0 + k];
            }
        }
        if (TRB) {
#pragma unroll
            for (int i = tid; i < BK * BN; i += NT) {
                int n = i / BK, k = i % BK;
                Bs[k][n] = B[(long)(n0 + n) * ldb + k0 + k];
            }
        } else {
#pragma unroll
            for (int i = tid; i < BK * BN; i += NT) {
                int k = i / BN, n = i % BN;
                Bs[k][n] = B[(long)(k0 + k) * ldb + n0 + n];
            }
        }
        __syncthreads();

#pragma unroll
        for (int k = 0; k < BK; k++) {
            float a[TM], b[TN];
#pragma unroll
            for (int i = 0; i < TM; i++) a[i] = As[k][ty * TM + i];
#pragma unroll
            for (int j = 0; j < TN; j++) b[j] = Bs[k][tx * TN + j];
#pragma unroll
            for (int i = 0; i < TM; i++)
#pragma unroll
                for (int j = 0; j < TN; j++)
                    acc[i][j] = fmaf(a[i], b[j], acc[i][j]);
        }
        __syncthreads();
    }

#pragma unroll
    for (int i = 0; i < TM; i++) {
        const int m = m0 + ty * TM + i;
#pragma unroll
        for (int j = 0; j < TN; j++) {
            const int n = n0 + tx * TN + j;
            const long idx = (long)m * ldc + n;
            float v = acc[i][j];
            if (ACC) v += C[idx];
            if (bias) v += bias[n];
            if (EPI == 1) v = 0.5f * v * (1.f + erff(v * 0.70710678118654752f));
            else if (EPI == 2) v = tanhf(v) * PI_F;
            else if (EPI == 3) v = (v > 20.f ? v : log1pf(expf(v))) + 0.1f;
            else if (EPI == 4) v += X[idx];
            else if (EPI == 5) v = (n <= m) ? v : 0.f;     // causal (local indices)
            else if (EPI == 6) {
                int l = z * M + m;                          // global sequence position
                v *= rsqrtf((float)(l + 1) * (float)KK);
            }
            C[idx] = v;
        }
    }
}

// ---------------------------------------------------------------------------
// phasors: Qc = [amp*cos(pq) | amp*sin(pq)], Kc = [amp*cos(pk) | amp*sin(pk)]
// ---------------------------------------------------------------------------
__global__ void phasor_k()
{
    int idx = blockIdx.x * blockDim.x + threadIdx.x;
    if (idx >= LL * KK) return;
    int l = idx / KK, k = idx % KK;
    float a = g_amp[idx];
    float s, c;
    sincosf(g_pk[idx], &s, &c);
    g_Kc[l * TWOK + k]      = a * c;
    g_Kc[l * TWOK + KK + k] = a * s;
    sincosf(g_pq[idx], &s, &c);
    g_Qc[l * TWOK + k]      = a * c;
    g_Qc[l * TWOK + KK + k] = a * s;
}

// ---------------------------------------------------------------------------
// exclusive prefix over chunks of G -> Sx (states seen by each chunk)
// ---------------------------------------------------------------------------
__global__ void scan_k()
{
    int idx = blockIdx.x * blockDim.x + threadIdx.x;   // < TWOK*DD = 65536
    if (idx >= TWOK * DD) return;
    float run = 0.f;
#pragma unroll
    for (int c = 0; c < NCH; c++) {
        g_Sx[c * (TWOK * DD) + idx] = run;
        run += g_G[c * (TWOK * DD) + idx];
    }
}

// ---------------------------------------------------------------------------
// LayerNorm over last dim (D=512), eps 1e-5. One block (256 thr) per row.
// ---------------------------------------------------------------------------
__global__ void ln_k(const float* __restrict__ in, const float* __restrict__ g,
                     const float* __restrict__ b, float* __restrict__ out)
{
    const int row = blockIdx.x;
    const int tid = threadIdx.x;
    const float* r = in + (long)row * DD;

    float v0 = r[tid], v1 = r[tid + 256];

    __shared__ float sh[256];
    sh[tid] = v0 + v1;
    __syncthreads();
#pragma unroll
    for (int o = 128; o > 0; o >>= 1) {
        if (tid < o) sh[tid] += sh[tid + o];
        __syncthreads();
    }
    float mu = sh[0] * (1.f / DD);
    __syncthreads();

    float d0 = v0 - mu, d1 = v1 - mu;
    sh[tid] = d0 * d0 + d1 * d1;
    __syncthreads();
#pragma unroll
    for (int o = 128; o > 0; o >>= 1) {
        if (tid < o) sh[tid] += sh[tid + o];
        __syncthreads();
    }
    float inv = rsqrtf(sh[0] * (1.f / DD) + 1e-5f);

    out[(long)row * DD + tid]       = d0 * inv * g[tid]       + b[tid];
    out[(long)row * DD + tid + 256] = d1 * inv * g[tid + 256] + b[tid + 256];
}

// ---------------------------------------------------------------------------
extern "C" void kernel_launch(void* const* d_in, const int* in_sizes, int n_in,
                              void* d_out, int out_size)
{
    const float* x     = (const float*)d_in[0];
    const float* ke_w1 = (const float*)d_in[1];
    const float* ke_b1 = (const float*)d_in[2];
    const float* ke_w2 = (const float*)d_in[3];
    const float* ke_b2 = (const float*)d_in[4];
    const float* qe_w1 = (const float*)d_in[5];
    const float* qe_b1 = (const float*)d_in[6];
    const float* qe_w2 = (const float*)d_in[7];
    const float* qe_b2 = (const float*)d_in[8];
    const float* amp_w = (const float*)d_in[9];
    const float* amp_b = (const float*)d_in[10];
    const float* v_w   = (const float*)d_in[11];
    const float* v_b   = (const float*)d_in[12];
    const float* ln_g  = (const float*)d_in[13];
    const float* ln_b  = (const float*)d_in[14];
    const float* out_w = (const float*)d_in[15];
    const float* out_b = (const float*)d_in[16];
    float* out = (float*)d_out;

    float *H, *pk, *pq, *amp, *V, *Qc, *Kc, *G, *Sx, *P, *ret, *rn;
    cudaGetSymbolAddress((void**)&H,   g_H);
    cudaGetSymbolAddress((void**)&pk,  g_pk);
    cudaGetSymbolAddress((void**)&pq,  g_pq);
    cudaGetSymbolAddress((void**)&amp, g_amp);
    cudaGetSymbolAddress((void**)&V,   g_V);
    cudaGetSymbolAddress((void**)&Qc,  g_Qc);
    cudaGetSymbolAddress((void**)&Kc,  g_Kc);
    cudaGetSymbolAddress((void**)&G,   g_G);
    cudaGetSymbolAddress((void**)&Sx,  g_Sx);
    cudaGetSymbolAddress((void**)&P,   g_P);
    cudaGetSymbolAddress((void**)&ret, g_ret);
    cudaGetSymbolAddress((void**)&rn,  g_rn);

    const dim3 T(256);

    // 1) H = gelu(x @ ke_w1 + ke_b1)        [2048x512]
    gemm_k<128,64,16,8,4, 1,false,false,false>
        <<<dim3(DD/64, LL/128, 1), T>>>(x, ke_w1, ke_b1, nullptr, H,
                                        LL, DD, DD, DD, DD, DD, 0, 0, 0);
    // 2) pk = tanh(H @ ke_w2 + ke_b2)*pi    [2048x64]
    gemm_k<32,64,16,2,4, 2,false,false,false>
        <<<dim3(KK/64, LL/32, 1), T>>>(H, ke_w2, ke_b2, nullptr, pk,
                                       LL, KK, DD, DD, KK, KK, 0, 0, 0);
    // 3) H = gelu(x @ qe_w1 + qe_b1)
    gemm_k<128,64,16,8,4, 1,false,false,false>
        <<<dim3(DD/64, LL/128, 1), T>>>(x, qe_w1, qe_b1, nullptr, H,
                                        LL, DD, DD, DD, DD, DD, 0, 0, 0);
    // 4) pq = tanh(H @ qe_w2 + qe_b2)*pi
    gemm_k<32,64,16,2,4, 2,false,false,false>
        <<<dim3(KK/64, LL/32, 1), T>>>(H, qe_w2, qe_b2, nullptr, pq,
                                       LL, KK, DD, DD, KK, KK, 0, 0, 0);
    // 5) amp = softplus(x @ amp_w + amp_b) + 0.1
    gemm_k<32,64,16,2,4, 3,false,false,false>
        <<<dim3(KK/64, LL/32, 1), T>>>(x, amp_w, amp_b, nullptr, amp,
                                       LL, KK, DD, DD, KK, KK, 0, 0, 0);
    // 6) V = x @ v_w + v_b
    gemm_k<128,64,16,8,4, 0,false,false,false>
        <<<dim3(DD/64, LL/128, 1), T>>>(x, v_w, v_b, nullptr, V,
                                        LL, DD, DD, DD, DD, DD, 0, 0, 0);
    // 7) phasors
    phasor_k<<<(LL*KK + 255)/256, 256>>>();

    // 8) G_c = Kc_c^T @ V_c   (batched over 16 chunks)  [128x512 each]
    gemm_k<128,64,16,8,4, 0,true,false,false>
        <<<dim3(DD/64, 1, NCH), T>>>(Kc, V, nullptr, nullptr, G,
                                     TWOK, DD, CH, TWOK, DD, DD,
                                     (long)CH*TWOK, (long)CH*DD, (long)TWOK*DD);
    // 9) exclusive chunk scan: Sx
    scan_k<<<(TWOK*DD + 255)/256, 256>>>();

    // 10) P_c = tril(Qc_c @ Kc_c^T)   [128x128 each]
    gemm_k<32,64,16,2,4, 5,false,true,false>
        <<<dim3(CH/64, CH/32, NCH), T>>>(Qc, Kc, nullptr, nullptr, P,
                                         CH, CH, TWOK, TWOK, TWOK, CH,
                                         (long)CH*TWOK, (long)CH*TWOK, (long)CH*CH);
    // 11) ret_c = Qc_c @ Sx_c
    gemm_k<128,64,16,8,4, 0,false,false,false>
        <<<dim3(DD/64, 1, NCH), T>>>(Qc, Sx, nullptr, nullptr, ret,
                                     CH, DD, TWOK, TWOK, DD, DD,
                                     (long)CH*TWOK, (long)TWOK*DD, (long)CH*DD);
    // 12) ret_c = (ret_c + P_c @ V_c) * rsqrt((l+1)*K)
    gemm_k<128,64,16,8,4, 6,false,false,true>
        <<<dim3(DD/64, 1, NCH), T>>>(P, V, nullptr, nullptr, ret,
                                     CH, DD, CH, CH, DD, DD,
                                     (long)CH*CH, (long)CH*DD, (long)CH*DD);
    // 13) rn = LayerNorm(ret) * g + b
    ln_k<<<LL, 256>>>(ret, ln_g, ln_b, rn);

    // 14) out = x + rn @ out_w + out_b
    gemm_k<128,64,16,8,4, 4,false,false,false>
        <<<dim3(DD/64, LL/128, 1), T>>>(rn, out_w, out_b, x, out,
                                        LL, DD, DD, DD, DD, DD, 0, 0, 0);
    (void)in_sizes; (void)n_in; (void)out_size;
}